// round 14
// baseline (speedup 1.0000x reference)
#include <cuda_runtime.h>
#include <cuda_fp16.h>
#include <math.h>
#include <stdint.h>

#define S_LEN 4096
#define B_SZ  64
#define EMB   128
#define DEC   128
#define FANIN 256
#define LDW   68            // u32 words per fp16 row: 136 halfs = 128 data + 8 pad
#define ROWB  272           // bytes per padded fp16 row
#define NCTA  148           // persistent grid: 1 CTA/SM (512 threads)
#define NPAIR 2048          // 2048 tile-pairs of 128 rows

// ---------------- scratch (no device allocation allowed) ----------------
__device__ float g_hproj[B_SZ * DEC];
__device__ float g_scores[B_SZ * S_LEN];
__device__ __align__(16) uint32_t g_we[128 * LDW];   // We fp16, [n][k] padded
__device__ int g_sync;

// ---------------- helpers ----------------
__device__ __forceinline__ uint32_t smem_u32(const void* p) {
    uint32_t a;
    asm("{ .reg .u64 t; cvta.to.shared.u64 t, %1; cvt.u32.u64 %0, t; }" : "=r"(a) : "l"(p));
    return a;
}
#define LDSM4(r, a) \
    asm volatile("ldmatrix.sync.aligned.m8n8.x4.shared.b16 {%0,%1,%2,%3}, [%4];" \
        : "=r"((r)[0]), "=r"((r)[1]), "=r"((r)[2]), "=r"((r)[3]) : "r"(a))

#define MMA16816(c, a, b0, b1) \
    asm volatile("mma.sync.aligned.m16n8k16.row.col.f32.f16.f16.f32 " \
        "{%0,%1,%2,%3},{%4,%5,%6,%7},{%8,%9},{%0,%1,%2,%3};" \
        : "+f"((c)[0]), "+f"((c)[1]), "+f"((c)[2]), "+f"((c)[3]) \
        : "r"((a)[0]), "r"((a)[1]), "r"((a)[2]), "r"((a)[3]), "r"(b0), "r"(b1))

__device__ __forceinline__ float tanh_approx(float x) {
    float t;
    asm("tanh.approx.f32 %0, %1;" : "=f"(t) : "f"(x));
    return t;
}
__device__ __forceinline__ uint32_t pack_h2(float lo, float hi) {
    uint32_t w;
    asm("cvt.rn.f16x2.f32 %0, %1, %2;" : "=r"(w) : "f"(hi), "f"(lo));  // lo -> low half
    return w;
}
__device__ __forceinline__ float2 unpack_h2(uint32_t w) {
    __half2 h = *reinterpret_cast<__half2*>(&w);
    return __half22float2(h);
}

// ---------------------------------------------------------------------------
// Fused prep: blocks 0..63 -> h_proj rows; blocks 64..95 -> We fp16 convert.
// ---------------------------------------------------------------------------
__global__ __launch_bounds__(256) void prep_kernel(const float* __restrict__ hidden,
                                                   const float* __restrict__ W,
                                                   const float* __restrict__ bias) {
    const int tid = threadIdx.x;
    if (blockIdx.x == 0 && tid == 0) g_sync = 0;

    if (blockIdx.x < B_SZ) {
        __shared__ float h[DEC];
        const int b = blockIdx.x;
        const int wid = tid >> 5, lane = tid & 31;
        if (tid < DEC) h[tid] = hidden[b * DEC + tid];
        __syncthreads();
        #pragma unroll
        for (int i = 0; i < 16; i++) {
            int d = wid * 16 + i;
            const float* w = W + d * FANIN;
            float sum = 0.f;
            #pragma unroll
            for (int e = lane; e < DEC; e += 32) sum = fmaf(h[e], w[e], sum);
            #pragma unroll
            for (int o = 16; o > 0; o >>= 1) sum += __shfl_xor_sync(0xffffffffu, sum, o);
            if (lane == 0) g_hproj[b * DEC + d] = sum + bias[d];
        }
    } else {
        int idx = (blockIdx.x - B_SZ) * 256 + tid;   // 8192 f16x2 words
        int n  = idx >> 6;
        int kp = idx & 63;
        float x0 = W[n * FANIN + DEC + 2 * kp];
        float x1 = W[n * FANIN + DEC + 2 * kp + 1];
        g_we[n * LDW + kp] = pack_h2(x0, x1);
    }
}

// ---------------------------------------------------------------------------
// persistent score kernel + fused softmax. 512 threads, 16 warps = (mw,nw) 4x4
// over a 128-row x 128-col tile (2 s per iter). B (We) fragments in registers.
// Tile row m -> batch b = m & 63, s = sp*2 + (m >> 6).
// ---------------------------------------------------------------------------
#define OFF_V    0                        // 512 B
#define OFF_PART 512                      // 128*4 f32 = 2048 B
#define OFF_HP   4096                     // 512 * 64 B (f16-packed per-thread) = 32768
#define OFF_X0   36864                    // 128 * ROWB = 34816
#define OFF_X1   71680                    // 34816
#define SMEM_BYTES 106496

extern __shared__ char smem[];

__global__ __launch_bounds__(512, 1) void score_kernel(const float* __restrict__ seq,
                                                       const float* __restrict__ vw,
                                                       const int* __restrict__ mask,
                                                       float* __restrict__ out) {
    const int tid  = threadIdx.x;
    const int wid  = tid >> 5;
    const int lane = tid & 31;
    const int mw = wid & 3;          // rows mw*32 .. mw*32+31 (2 m16 tiles)
    const int nw = wid >> 2;         // cols nw*32 .. nw*32+31 (2 n16 = 4 n8)
    const int j = lane >> 3, r = lane & 7;
    const int q = lane & 3;

    // ---- stage We f16 into X0 region (temporary), v into smem ----
    {
        const int4* sh = (const int4*)g_we;
        int4* dh = (int4*)(smem + OFF_X0);
        for (int i = tid; i < 2176; i += 512) dh[i] = sh[i];
    }
    if (tid < 128) ((float*)(smem + OFF_V))[tid] = vw[tid];

    // ---- pack this thread's h_proj values into smem (f16x2, contiguous) ----
    // NOTE: tile row ra maps to batch b = ra & 63 (rows 64..127 are the 2nd s).
    {
        uint32_t* hpw = (uint32_t*)(smem + OFF_HP + tid * 64);
        #pragma unroll
        for (int i = 0; i < 2; i++) {
            int ra = mw * 32 + i * 16 + (lane >> 2);
            int ba = ra & 63;                 // batch index for row ra
            int bb = (ra + 8) & 63;           // batch index for row ra+8
            #pragma unroll
            for (int nt = 0; nt < 4; nt++) {
                int c0 = nw * 32 + nt * 8 + 2 * q;
                hpw[i * 8 + nt * 2]     = pack_h2(g_hproj[ba * DEC + c0], g_hproj[ba * DEC + c0 + 1]);
                hpw[i * 8 + nt * 2 + 1] = pack_h2(g_hproj[bb * DEC + c0], g_hproj[bb * DEC + c0 + 1]);
            }
        }
    }
    __syncthreads();

    // ---- load B fragments into registers (once) ----
    uint32_t bfr[2][8][4];
    {
        const uint32_t b_ad = smem_u32(smem + OFF_X0)
                            + (uint32_t)(nw * 32 + (j >> 1) * 8 + r) * ROWB + (uint32_t)(j & 1) * 16;
        #pragma unroll
        for (int p = 0; p < 2; p++)
            #pragma unroll
            for (int k = 0; k < 8; k++)
                LDSM4(bfr[p][k], b_ad + (uint32_t)p * (16 * ROWB) + (uint32_t)k * 32);
    }
    __syncthreads();   // X0 free for reuse

    const uint32_t a_base = smem_u32(smem + OFF_X0)
                          + (uint32_t)(mw * 32 + r + 8 * (j & 1)) * ROWB + (uint32_t)(j >> 1) * 16;
    float* part = (float*)(smem + OFF_PART);
    const float* vs = (const float*)(smem + OFF_V);
    const char* hpb = smem + OFF_HP + tid * 64;

    // ---- prologue: prefetch first X tile, converting to f16x2 on arrival ----
    uint32_t xrh[16];
    {
        const float4* src = (const float4*)(seq + (size_t)blockIdx.x * 128 * EMB);
        #pragma unroll
        for (int ii = 0; ii < 8; ii++) {
            float4 x = src[tid + ii * 512];
            xrh[2 * ii]     = pack_h2(x.x, x.y);
            xrh[2 * ii + 1] = pack_h2(x.z, x.w);
        }
    }

    uint32_t parity = 0;
    for (int sp = blockIdx.x; sp < NPAIR; sp += NCTA) {
        const uint32_t xoff = parity ? (uint32_t)(OFF_X1 - OFF_X0) : 0u;

        // ---- store converted tile to smem buffer[parity] ----
        #pragma unroll
        for (int ii = 0; ii < 8; ii++) {
            int i = tid + ii * 512;              // 4096 float4-groups -> rows of 32
            int row = i >> 5, c4 = i & 31;
            *(uint2*)(smem + OFF_X0 + xoff + (uint32_t)row * ROWB + (uint32_t)c4 * 8)
                = make_uint2(xrh[2 * ii], xrh[2 * ii + 1]);
        }
        __syncthreads();

        // ---- prefetch + convert next tile while MMA runs ----
        int spn = sp + NCTA;
        if (spn < NPAIR) {
            const float4* srcn = (const float4*)(seq + (size_t)spn * 128 * EMB);
            #pragma unroll
            for (int ii = 0; ii < 8; ii++) {
                float4 x = srcn[tid + ii * 512];
                xrh[2 * ii]     = pack_h2(x.x, x.y);
                xrh[2 * ii + 1] = pack_h2(x.z, x.w);
            }
        }

        // ---- GEMM: acc = A*B (B from registers) ----
        float acc[2][4][4];
        #pragma unroll
        for (int i = 0; i < 2; i++)
            #pragma unroll
            for (int nt = 0; nt < 4; nt++)
                #pragma unroll
                for (int qq = 0; qq < 4; qq++) acc[i][nt][qq] = 0.f;

        const uint32_t a_ad = a_base + xoff;
        #pragma unroll
        for (int k = 0; k < 8; k++) {
            uint32_t a0[4], a1[4];
            LDSM4(a0, a_ad + (uint32_t)k * 32);
            LDSM4(a1, a_ad + 16 * ROWB + (uint32_t)k * 32);
            #pragma unroll
            for (int p = 0; p < 2; p++) {
                MMA16816(acc[0][2 * p],     a0, bfr[p][k][0], bfr[p][k][1]);
                MMA16816(acc[0][2 * p + 1], a0, bfr[p][k][2], bfr[p][k][3]);
                MMA16816(acc[1][2 * p],     a1, bfr[p][k][0], bfr[p][k][1]);
                MMA16816(acc[1][2 * p + 1], a1, bfr[p][k][2], bfr[p][k][3]);
            }
        }

        // ---- epilogue: +hp, tanh.approx, v-dot, quad reduce ----
        #pragma unroll
        for (int i = 0; i < 2; i++) {
            uint4 wa = *(const uint4*)(hpb + i * 32);        // nt0: w01,w23 ; nt1: w01,w23
            uint4 wb = *(const uint4*)(hpb + i * 32 + 16);   // nt2, nt3
            uint32_t w01[4] = { wa.x, wa.z, wb.x, wb.z };
            uint32_t w23[4] = { wa.y, wa.w, wb.y, wb.w };
            float p0 = 0.f, p1 = 0.f;
            #pragma unroll
            for (int nt = 0; nt < 4; nt++) {
                int c0 = nw * 32 + nt * 8 + 2 * q;
                float v0 = vs[c0], v1 = vs[c0 + 1];
                float2 hA = unpack_h2(w01[nt]);
                float2 hB = unpack_h2(w23[nt]);
                p0 = fmaf(v0, tanh_approx(acc[i][nt][0] + hA.x), p0);
                p0 = fmaf(v1, tanh_approx(acc[i][nt][1] + hA.y), p0);
                p1 = fmaf(v0, tanh_approx(acc[i][nt][2] + hB.x), p1);
                p1 = fmaf(v1, tanh_approx(acc[i][nt][3] + hB.y), p1);
            }
            p0 += __shfl_xor_sync(0xffffffffu, p0, 1);
            p0 += __shfl_xor_sync(0xffffffffu, p0, 2);
            p1 += __shfl_xor_sync(0xffffffffu, p1, 1);
            p1 += __shfl_xor_sync(0xffffffffu, p1, 2);
            if (q == 0) {
                int ra = mw * 32 + i * 16 + (lane >> 2);
                part[ra * 4 + nw] = p0;
                part[(ra + 8) * 4 + nw] = p1;
            }
        }
        __syncthreads();
        if (tid < 128) {
            float4 pr = *(const float4*)(part + tid * 4);
            g_scores[(tid & 63) * S_LEN + sp * 2 + (tid >> 6)] = (pr.x + pr.y) + (pr.z + pr.w);
        }
        parity ^= 1u;
    }

    // ================= fused softmax (grid-wide sync via counter) ==========
    __threadfence();
    if (tid == 0) atomicAdd(&g_sync, 1);
    if (blockIdx.x >= B_SZ) return;

    if (tid == 0) {
        int v;
        do {
            asm volatile("ld.acquire.gpu.s32 %0, [%1];" : "=r"(v) : "l"(&g_sync) : "memory");
        } while (v < NCTA);
    }
    __syncthreads();

    float* ex = (float*)smem;            // 16 KB, smem now free
    __shared__ float red[16];
    const int b = blockIdx.x;
    const float* sc = g_scores + b * S_LEN;
    const int*   mk = mask + b * S_LEN;

    float mx = -1e30f;
    #pragma unroll
    for (int i = 0; i < 8; i++) {
        int s = tid + i * 512;
        float v = (mk[s] == 0) ? -1e10f : sc[s];
        ex[s] = v;
        mx = fmaxf(mx, v);
    }
    #pragma unroll
    for (int o = 16; o > 0; o >>= 1) mx = fmaxf(mx, __shfl_xor_sync(0xffffffffu, mx, o));
    if (lane == 0) red[wid] = mx;
    __syncthreads();
    if (tid < 16) {
        float m = red[tid];
        #pragma unroll
        for (int o = 8; o > 0; o >>= 1) m = fmaxf(m, __shfl_xor_sync(0xffffu, m, o));
        red[tid] = m;
    }
    __syncthreads();
    mx = red[0];

    float sum = 0.f;
    #pragma unroll
    for (int i = 0; i < 8; i++) {
        int s = tid + i * 512;
        float e = __expf(ex[s] - mx);
        ex[s] = e;
        sum += e;
    }
    #pragma unroll
    for (int o = 16; o > 0; o >>= 1) sum += __shfl_xor_sync(0xffffffffu, sum, o);
    __syncthreads();
    if (lane == 0) red[wid] = sum;
    __syncthreads();
    if (tid < 16) {
        float m = red[tid];
        #pragma unroll
        for (int o = 8; o > 0; o >>= 1) m += __shfl_xor_sync(0xffffu, m, o);
        red[tid] = m;
    }
    __syncthreads();
    float inv = 1.f / red[0];

    #pragma unroll
    for (int i = 0; i < 8; i++) {
        int s = tid + i * 512;
        out[b * S_LEN + s] = ex[s] * inv;
    }
}

// ---------------------------------------------------------------------------
extern "C" void kernel_launch(void* const* d_in, const int* in_sizes, int n_in,
                              void* d_out, int out_size) {
    const float* hidden = (const float*)d_in[0];
    const float* seq    = (const float*)d_in[1];
    const int*   mask   = (const int*)d_in[2];
    const float* W      = (const float*)d_in[3];
    const float* bias   = (const float*)d_in[4];
    const float* vw     = (const float*)d_in[5];
    float* out = (float*)d_out;

    cudaFuncSetAttribute(score_kernel, cudaFuncAttributeMaxDynamicSharedMemorySize, SMEM_BYTES);

    prep_kernel<<<96, 256>>>(hidden, W, bias);
    score_kernel<<<NCTA, 512, SMEM_BYTES>>>(seq, vw, mask, out);
}

// round 16
// speedup vs baseline: 1.0679x; 1.0679x over previous
#include <cuda_runtime.h>
#include <cuda_fp16.h>
#include <math.h>
#include <stdint.h>

#define S_LEN 4096
#define B_SZ  64
#define EMB   128
#define DEC   128
#define FANIN 256
#define LDW   68            // u32 words per fp16 row: 136 halfs = 128 data + 8 pad
#define ROWB  272           // bytes per padded fp16 row
#define NCTA  296           // persistent grid: 2 CTAs/SM x 148 SMs

// ---------------- scratch (no device allocation allowed) ----------------
__device__ float g_hproj[B_SZ * DEC];
__device__ float g_scores[B_SZ * S_LEN];
__device__ __align__(16) uint32_t g_we[128 * LDW];   // We fp16, [n][k] padded
__device__ int g_sync;

// ---------------- helpers ----------------
__device__ __forceinline__ uint32_t smem_u32(const void* p) {
    uint32_t a;
    asm("{ .reg .u64 t; cvta.to.shared.u64 t, %1; cvt.u32.u64 %0, t; }" : "=r"(a) : "l"(p));
    return a;
}
#define LDSM4(r, a) \
    asm volatile("ldmatrix.sync.aligned.m8n8.x4.shared.b16 {%0,%1,%2,%3}, [%4];" \
        : "=r"((r)[0]), "=r"((r)[1]), "=r"((r)[2]), "=r"((r)[3]) : "r"(a))

#define MMA16816(c, a, b0, b1) \
    asm volatile("mma.sync.aligned.m16n8k16.row.col.f32.f16.f16.f32 " \
        "{%0,%1,%2,%3},{%4,%5,%6,%7},{%8,%9},{%0,%1,%2,%3};" \
        : "+f"((c)[0]), "+f"((c)[1]), "+f"((c)[2]), "+f"((c)[3]) \
        : "r"((a)[0]), "r"((a)[1]), "r"((a)[2]), "r"((a)[3]), "r"(b0), "r"(b1))

__device__ __forceinline__ float tanh_approx(float x) {
    float t;
    asm("tanh.approx.f32 %0, %1;" : "=f"(t) : "f"(x));
    return t;
}
__device__ __forceinline__ uint32_t pack_h2(float lo, float hi) {
    uint32_t w;
    asm("cvt.rn.f16x2.f32 %0, %1, %2;" : "=r"(w) : "f"(hi), "f"(lo));  // lo -> low half
    return w;
}
__device__ __forceinline__ float2 unpack_h2(uint32_t w) {
    __half2 h = *reinterpret_cast<__half2*>(&w);
    return __half22float2(h);
}

// ---------------------------------------------------------------------------
// Fused prep: blocks 0..63 -> h_proj rows; blocks 64..95 -> We fp16 convert.
// ---------------------------------------------------------------------------
__global__ __launch_bounds__(256) void prep_kernel(const float* __restrict__ hidden,
                                                   const float* __restrict__ W,
                                                   const float* __restrict__ bias) {
    const int tid = threadIdx.x;
    if (blockIdx.x == 0 && tid == 0) g_sync = 0;

    if (blockIdx.x < B_SZ) {
        __shared__ float h[DEC];
        const int b = blockIdx.x;
        const int wid = tid >> 5, lane = tid & 31;
        if (tid < DEC) h[tid] = hidden[b * DEC + tid];
        __syncthreads();
        #pragma unroll
        for (int i = 0; i < 16; i++) {
            int d = wid * 16 + i;
            const float* w = W + d * FANIN;
            float sum = 0.f;
            #pragma unroll
            for (int e = lane; e < DEC; e += 32) sum = fmaf(h[e], w[e], sum);
            #pragma unroll
            for (int o = 16; o > 0; o >>= 1) sum += __shfl_xor_sync(0xffffffffu, sum, o);
            if (lane == 0) g_hproj[b * DEC + d] = sum + bias[d];
        }
    } else {
        int idx = (blockIdx.x - B_SZ) * 256 + tid;   // 8192 f16x2 words
        int n  = idx >> 6;
        int kp = idx & 63;
        float x0 = W[n * FANIN + DEC + 2 * kp];
        float x1 = W[n * FANIN + DEC + 2 * kp + 1];
        g_we[n * LDW + kp] = pack_h2(x0, x1);
    }
}

// ---------------------------------------------------------------------------
// persistent score kernel + fused softmax. 256 threads, 8 warps = (mp 2 x nq 4)
// over a 64-row x 128-col tile (1 s per iter). B (We) fragments in registers.
// 2 CTAs/SM for cross-CTA phase overlap.
// ---------------------------------------------------------------------------
#define OFF_V    0                        // 512 B
#define OFF_PART 512                      // 256 f32 = 1024 B
#define OFF_HP   2048                     // 256 * 64 B (f16-packed per-thread) = 16384
#define OFF_X0   18432                    // 64 * ROWB = 17408
#define OFF_X1   35840                    // 17408  (X0+X1 contiguous = 34816 = full We for staging)
#define SMEM_BYTES 53248

extern __shared__ char smem[];

__global__ __launch_bounds__(256, 2) void score_kernel(const float* __restrict__ seq,
                                                       const float* __restrict__ vw,
                                                       const int* __restrict__ mask,
                                                       float* __restrict__ out) {
    const int tid  = threadIdx.x;
    const int wid  = tid >> 5;
    const int lane = tid & 31;
    const int mp = wid & 1;          // rows mp*32 .. mp*32+31 (2 m16 tiles)
    const int nq = wid >> 1;         // cols nq*32 .. nq*32+31 (2 n16 = 4 n8)
    const int j = lane >> 3, r = lane & 7;
    const int q = lane & 3;

    // ---- stage We f16 into X0+X1 region (temporary, contiguous 34816 B) ----
    {
        const int4* sh = (const int4*)g_we;
        int4* dh = (int4*)(smem + OFF_X0);
        for (int i = tid; i < 2176; i += 256) dh[i] = sh[i];
    }
    if (tid < 128) ((float*)(smem + OFF_V))[tid] = vw[tid];

    // ---- pack this thread's h_proj into smem (f16x2, per-thread contiguous) ----
    {
        uint32_t* hpw = (uint32_t*)(smem + OFF_HP + tid * 64);
        #pragma unroll
        for (int i = 0; i < 2; i++) {
            int ra = mp * 32 + i * 16 + (lane >> 2);   // 64-row tile: row == batch
            #pragma unroll
            for (int nt = 0; nt < 4; nt++) {
                int c0 = nq * 32 + nt * 8 + 2 * q;
                hpw[i * 8 + nt * 2]     = pack_h2(g_hproj[ra * DEC + c0],       g_hproj[ra * DEC + c0 + 1]);
                hpw[i * 8 + nt * 2 + 1] = pack_h2(g_hproj[(ra + 8) * DEC + c0], g_hproj[(ra + 8) * DEC + c0 + 1]);
            }
        }
    }
    __syncthreads();

    // ---- load B fragments into registers (once) ----
    uint32_t bfr[2][8][4];
    {
        const uint32_t b_ad = smem_u32(smem + OFF_X0)
                            + (uint32_t)(nq * 32 + (j >> 1) * 8 + r) * ROWB + (uint32_t)(j & 1) * 16;
        #pragma unroll
        for (int p = 0; p < 2; p++)
            #pragma unroll
            for (int k = 0; k < 8; k++)
                LDSM4(bfr[p][k], b_ad + (uint32_t)p * (16 * ROWB) + (uint32_t)k * 32);
    }
    __syncthreads();   // X0/X1 free for reuse

    const uint32_t a_base = smem_u32(smem + OFF_X0)
                          + (uint32_t)(mp * 32 + r + 8 * (j & 1)) * ROWB + (uint32_t)(j >> 1) * 16;
    float* part = (float*)(smem + OFF_PART);
    const float* vs = (const float*)(smem + OFF_V);
    const char* hpb = smem + OFF_HP + tid * 64;

    // ---- prologue: prefetch first X tile, converting to f16x2 on arrival ----
    uint32_t xrh[16];
    {
        const float4* src = (const float4*)(seq + (size_t)blockIdx.x * B_SZ * EMB);
        #pragma unroll
        for (int ii = 0; ii < 8; ii++) {
            float4 x = src[tid + ii * 256];
            xrh[2 * ii]     = pack_h2(x.x, x.y);
            xrh[2 * ii + 1] = pack_h2(x.z, x.w);
        }
    }

    uint32_t parity = 0;
    for (int s = blockIdx.x; s < S_LEN; s += NCTA) {
        const uint32_t xoff = parity ? (uint32_t)(OFF_X1 - OFF_X0) : 0u;

        // ---- store converted tile to smem buffer[parity] ----
        #pragma unroll
        for (int ii = 0; ii < 8; ii++) {
            int i = tid + ii * 256;              // 2048 float4-groups -> 64 rows of 32
            int row = i >> 5, c4 = i & 31;
            *(uint2*)(smem + OFF_X0 + xoff + (uint32_t)row * ROWB + (uint32_t)c4 * 8)
                = make_uint2(xrh[2 * ii], xrh[2 * ii + 1]);
        }
        __syncthreads();

        // ---- prefetch + convert next tile while MMA runs ----
        int sn = s + NCTA;
        if (sn < S_LEN) {
            const float4* srcn = (const float4*)(seq + (size_t)sn * B_SZ * EMB);
            #pragma unroll
            for (int ii = 0; ii < 8; ii++) {
                float4 x = srcn[tid + ii * 256];
                xrh[2 * ii]     = pack_h2(x.x, x.y);
                xrh[2 * ii + 1] = pack_h2(x.z, x.w);
            }
        }

        // ---- GEMM: acc = A*B (B from registers) ----
        float acc[2][4][4];
        #pragma unroll
        for (int i = 0; i < 2; i++)
            #pragma unroll
            for (int nt = 0; nt < 4; nt++)
                #pragma unroll
                for (int qq = 0; qq < 4; qq++) acc[i][nt][qq] = 0.f;

        const uint32_t a_ad = a_base + xoff;
        #pragma unroll
        for (int k = 0; k < 8; k++) {
            uint32_t a0[4], a1[4];
            LDSM4(a0, a_ad + (uint32_t)k * 32);
            LDSM4(a1, a_ad + 16 * ROWB + (uint32_t)k * 32);
            #pragma unroll
            for (int p = 0; p < 2; p++) {
                MMA16816(acc[0][2 * p],     a0, bfr[p][k][0], bfr[p][k][1]);
                MMA16816(acc[0][2 * p + 1], a0, bfr[p][k][2], bfr[p][k][3]);
                MMA16816(acc[1][2 * p],     a1, bfr[p][k][0], bfr[p][k][1]);
                MMA16816(acc[1][2 * p + 1], a1, bfr[p][k][2], bfr[p][k][3]);
            }
        }

        // ---- epilogue: +hp, tanh.approx, v-dot, quad reduce ----
        #pragma unroll
        for (int i = 0; i < 2; i++) {
            uint4 wa = *(const uint4*)(hpb + i * 32);
            uint4 wb = *(const uint4*)(hpb + i * 32 + 16);
            uint32_t w01[4] = { wa.x, wa.z, wb.x, wb.z };
            uint32_t w23[4] = { wa.y, wa.w, wb.y, wb.w };
            float p0 = 0.f, p1 = 0.f;
            #pragma unroll
            for (int nt = 0; nt < 4; nt++) {
                int c0 = nq * 32 + nt * 8 + 2 * q;
                float v0 = vs[c0], v1 = vs[c0 + 1];
                float2 hA = unpack_h2(w01[nt]);
                float2 hB = unpack_h2(w23[nt]);
                p0 = fmaf(v0, tanh_approx(acc[i][nt][0] + hA.x), p0);
                p0 = fmaf(v1, tanh_approx(acc[i][nt][1] + hA.y), p0);
                p1 = fmaf(v0, tanh_approx(acc[i][nt][2] + hB.x), p1);
                p1 = fmaf(v1, tanh_approx(acc[i][nt][3] + hB.y), p1);
            }
            p0 += __shfl_xor_sync(0xffffffffu, p0, 1);
            p0 += __shfl_xor_sync(0xffffffffu, p0, 2);
            p1 += __shfl_xor_sync(0xffffffffu, p1, 1);
            p1 += __shfl_xor_sync(0xffffffffu, p1, 2);
            if (q == 0) {
                int ra = mp * 32 + i * 16 + (lane >> 2);
                part[nq * 64 + ra] = p0;
                part[nq * 64 + ra + 8] = p1;
            }
        }
        __syncthreads();
        if (tid < 64)
            g_scores[tid * S_LEN + s] = (part[tid] + part[64 + tid])
                                      + (part[128 + tid] + part[192 + tid]);
        parity ^= 1u;   // next convert goes to the other buffer (no 3rd sync)
    }

    // ================= fused softmax (grid-wide sync via counter) ==========
    __threadfence();
    if (tid == 0) atomicAdd(&g_sync, 1);
    if (blockIdx.x >= B_SZ) return;

    if (tid == 0) {
        int v;
        do {
            asm volatile("ld.acquire.gpu.s32 %0, [%1];" : "=r"(v) : "l"(&g_sync) : "memory");
        } while (v < NCTA);
    }
    __syncthreads();

    float* ex = (float*)smem;            // 16 KB, smem now free
    __shared__ float red[8];
    const int b = blockIdx.x;
    const float* sc = g_scores + b * S_LEN;
    const int*   mk = mask + b * S_LEN;

    float mx = -1e30f;
    #pragma unroll
    for (int i = 0; i < 16; i++) {
        int s = tid + i * 256;
        float v = (mk[s] == 0) ? -1e10f : sc[s];
        ex[s] = v;
        mx = fmaxf(mx, v);
    }
    #pragma unroll
    for (int o = 16; o > 0; o >>= 1) mx = fmaxf(mx, __shfl_xor_sync(0xffffffffu, mx, o));
    if (lane == 0) red[wid] = mx;
    __syncthreads();
    if (tid < 8) {
        float m = red[tid];
        #pragma unroll
        for (int o = 4; o > 0; o >>= 1) m = fmaxf(m, __shfl_xor_sync(0xffu, m, o));
        red[tid] = m;
    }
    __syncthreads();
    mx = red[0];

    float sum = 0.f;
    #pragma unroll
    for (int i = 0; i < 16; i++) {
        int s = tid + i * 256;
        float e = __expf(ex[s] - mx);
        ex[s] = e;
        sum += e;
    }
    #pragma unroll
    for (int o = 16; o > 0; o >>= 1) sum += __shfl_xor_sync(0xffffffffu, sum, o);
    __syncthreads();
    if (lane == 0) red[wid] = sum;
    __syncthreads();
    if (tid < 8) {
        float m = red[tid];
        #pragma unroll
        for (int o = 4; o > 0; o >>= 1) m += __shfl_xor_sync(0xffu, m, o);
        red[tid] = m;
    }
    __syncthreads();
    float inv = 1.f / red[0];

    #pragma unroll
    for (int i = 0; i < 16; i++) {
        int s = tid + i * 256;
        out[b * S_LEN + s] = ex[s] * inv;
    }
}

// ---------------------------------------------------------------------------
extern "C" void kernel_launch(void* const* d_in, const int* in_sizes, int n_in,
                              void* d_out, int out_size) {
    const float* hidden = (const float*)d_in[0];
    const float* seq    = (const float*)d_in[1];
    const int*   mask   = (const int*)d_in[2];
    const float* W      = (const float*)d_in[3];
    const float* bias   = (const float*)d_in[4];
    const float* vw     = (const float*)d_in[5];
    float* out = (float*)d_out;

    cudaFuncSetAttribute(score_kernel, cudaFuncAttributeMaxDynamicSharedMemorySize, SMEM_BYTES);

    prep_kernel<<<96, 256>>>(hidden, W, bias);
    score_kernel<<<NCTA, 256, SMEM_BYTES>>>(seq, vw, mask, out);
}

// round 17
// speedup vs baseline: 1.0768x; 1.0083x over previous
#include <cuda_runtime.h>
#include <cuda_fp16.h>
#include <math.h>
#include <stdint.h>

#define S_LEN 4096
#define B_SZ  64
#define EMB   128
#define DEC   128
#define FANIN 256
#define LDW   68            // u32 words per fp16 row: 136 halfs = 128 data + 8 pad
#define ROWB  272           // bytes per padded fp16 row
#define NCTA  296           // persistent grid: 2 CTAs/SM x 148 SMs

// ---------------- scratch (no device allocation allowed) ----------------
__device__ float g_hproj[B_SZ * DEC];
__device__ float g_scores[B_SZ * S_LEN];
__device__ __align__(16) uint32_t g_we[128 * LDW];   // We fp16, [n][k] padded
__device__ int g_sync;

// ---------------- helpers ----------------
__device__ __forceinline__ uint32_t smem_u32(const void* p) {
    uint32_t a;
    asm("{ .reg .u64 t; cvta.to.shared.u64 t, %1; cvt.u32.u64 %0, t; }" : "=r"(a) : "l"(p));
    return a;
}
#define LDSM4(r, a) \
    asm volatile("ldmatrix.sync.aligned.m8n8.x4.shared.b16 {%0,%1,%2,%3}, [%4];" \
        : "=r"((r)[0]), "=r"((r)[1]), "=r"((r)[2]), "=r"((r)[3]) : "r"(a))

#define MMA16816(c, a, b0, b1) \
    asm volatile("mma.sync.aligned.m16n8k16.row.col.f32.f16.f16.f32 " \
        "{%0,%1,%2,%3},{%4,%5,%6,%7},{%8,%9},{%0,%1,%2,%3};" \
        : "+f"((c)[0]), "+f"((c)[1]), "+f"((c)[2]), "+f"((c)[3]) \
        : "r"((a)[0]), "r"((a)[1]), "r"((a)[2]), "r"((a)[3]), "r"(b0), "r"(b1))

#define CP_ASYNC16(sm, gm) \
    asm volatile("cp.async.cg.shared.global [%0], [%1], 16;" :: "r"(sm), "l"(gm))
#define CP_COMMIT() asm volatile("cp.async.commit_group;" ::: "memory")
#define CP_WAIT0()  asm volatile("cp.async.wait_group 0;" ::: "memory")

__device__ __forceinline__ float tanh_approx(float x) {
    float t;
    asm("tanh.approx.f32 %0, %1;" : "=f"(t) : "f"(x));
    return t;
}
__device__ __forceinline__ uint32_t pack_h2(float lo, float hi) {
    uint32_t w;
    asm("cvt.rn.f16x2.f32 %0, %1, %2;" : "=r"(w) : "f"(hi), "f"(lo));  // lo -> low half
    return w;
}
__device__ __forceinline__ float2 unpack_h2(uint32_t w) {
    __half2 h = *reinterpret_cast<__half2*>(&w);
    return __half22float2(h);
}

// ---------------------------------------------------------------------------
// Fused prep: blocks 0..63 -> h_proj rows; blocks 64..95 -> We fp16 convert.
// ---------------------------------------------------------------------------
__global__ __launch_bounds__(256) void prep_kernel(const float* __restrict__ hidden,
                                                   const float* __restrict__ W,
                                                   const float* __restrict__ bias) {
    const int tid = threadIdx.x;
    if (blockIdx.x == 0 && tid == 0) g_sync = 0;

    if (blockIdx.x < B_SZ) {
        __shared__ float h[DEC];
        const int b = blockIdx.x;
        const int wid = tid >> 5, lane = tid & 31;
        if (tid < DEC) h[tid] = hidden[b * DEC + tid];
        __syncthreads();
        #pragma unroll
        for (int i = 0; i < 16; i++) {
            int d = wid * 16 + i;
            const float* w = W + d * FANIN;
            float sum = 0.f;
            #pragma unroll
            for (int e = lane; e < DEC; e += 32) sum = fmaf(h[e], w[e], sum);
            #pragma unroll
            for (int o = 16; o > 0; o >>= 1) sum += __shfl_xor_sync(0xffffffffu, sum, o);
            if (lane == 0) g_hproj[b * DEC + d] = sum + bias[d];
        }
    } else {
        int idx = (blockIdx.x - B_SZ) * 256 + tid;   // 8192 f16x2 words
        int n  = idx >> 6;
        int kp = idx & 63;
        float x0 = W[n * FANIN + DEC + 2 * kp];
        float x1 = W[n * FANIN + DEC + 2 * kp + 1];
        g_we[n * LDW + kp] = pack_h2(x0, x1);
    }
}

// ---------------------------------------------------------------------------
// persistent score kernel + fused softmax. 256 threads, 8 warps = (mp 2 x nq 4)
// warp tile m32 x n32 over a 64-row tile. B (We) fragments in registers.
// X prefetch: cp.async gmem->f32 staging smem (0 registers), convert next iter.
// 2 CTAs/SM for cross-CTA phase overlap.
// ---------------------------------------------------------------------------
#define OFF_V     0                       // 512 B
#define OFF_PART  512                     // 1024 B
#define OFF_HP    2048                    // 256 * 64 B = 16384
#define OFF_X0    18432                   // 17408
#define OFF_X1    35840                   // 17408 (X0+X1 contiguous = We staging)
#define OFF_STAGE 53248                   // 64*128*4 = 32768 (f32 staging)
#define SMEM_BYTES 86016

extern __shared__ char smem[];

__global__ __launch_bounds__(256, 2) void score_kernel(const float* __restrict__ seq,
                                                       const float* __restrict__ vw,
                                                       const int* __restrict__ mask,
                                                       float* __restrict__ out) {
    const int tid  = threadIdx.x;
    const int wid  = tid >> 5;
    const int lane = tid & 31;
    const int mp = wid & 1;          // rows mp*32 .. mp*32+31 (2 m16 tiles)
    const int nq = wid >> 1;         // cols nq*32 .. nq*32+31 (4 n8)
    const int j = lane >> 3, r = lane & 7;
    const int q = lane & 3;

    // ---- stage We f16 into X0+X1 region (temporary, contiguous 34816 B) ----
    {
        const int4* sh = (const int4*)g_we;
        int4* dh = (int4*)(smem + OFF_X0);
        for (int i = tid; i < 2176; i += 256) dh[i] = sh[i];
    }
    if (tid < 128) ((float*)(smem + OFF_V))[tid] = vw[tid];

    // ---- pack this thread's h_proj into smem (f16x2, per-thread contiguous) ----
    {
        uint32_t* hpw = (uint32_t*)(smem + OFF_HP + tid * 64);
        #pragma unroll
        for (int i = 0; i < 2; i++) {
            int ra = mp * 32 + i * 16 + (lane >> 2);   // 64-row tile: row == batch
            #pragma unroll
            for (int nt = 0; nt < 4; nt++) {
                int c0 = nq * 32 + nt * 8 + 2 * q;
                hpw[i * 8 + nt * 2]     = pack_h2(g_hproj[ra * DEC + c0],       g_hproj[ra * DEC + c0 + 1]);
                hpw[i * 8 + nt * 2 + 1] = pack_h2(g_hproj[(ra + 8) * DEC + c0], g_hproj[(ra + 8) * DEC + c0 + 1]);
            }
        }
    }
    __syncthreads();

    // ---- load B fragments into registers (once) ----
    uint32_t bfr[2][8][4];
    {
        const uint32_t b_ad = smem_u32(smem + OFF_X0)
                            + (uint32_t)(nq * 32 + (j >> 1) * 8 + r) * ROWB + (uint32_t)(j & 1) * 16;
        #pragma unroll
        for (int p = 0; p < 2; p++)
            #pragma unroll
            for (int k = 0; k < 8; k++)
                LDSM4(bfr[p][k], b_ad + (uint32_t)p * (16 * ROWB) + (uint32_t)k * 32);
    }
    __syncthreads();   // X0/X1 free for reuse

    const uint32_t a_base  = smem_u32(smem + OFF_X0)
                           + (uint32_t)(mp * 32 + r + 8 * (j & 1)) * ROWB + (uint32_t)(j >> 1) * 16;
    const uint32_t stage_b = smem_u32(smem + OFF_STAGE);
    float* part = (float*)(smem + OFF_PART);
    const float* vs = (const float*)(smem + OFF_V);
    const char* hpb = smem + OFF_HP + tid * 64;

    // ---- prologue: cp.async first X tile into f32 staging ----
    {
        const char* src = (const char*)(seq + (size_t)blockIdx.x * B_SZ * EMB) + tid * 16;
        uint32_t dst = stage_b + tid * 16;
        #pragma unroll
        for (int ii = 0; ii < 8; ii++)
            CP_ASYNC16(dst + ii * 4096, src + ii * 4096);
        CP_COMMIT();
        CP_WAIT0();
    }
    __syncthreads();

    uint32_t parity = 0;
    for (int s = blockIdx.x; s < S_LEN; s += NCTA) {
        const uint32_t xoff = parity ? (uint32_t)(OFF_X1 - OFF_X0) : 0u;

        // ---- convert: f32 staging -> f16 buffer[parity] ----
        #pragma unroll
        for (int ii = 0; ii < 8; ii++) {
            int i = tid + ii * 256;              // 2048 float4-groups: 64 rows x 32
            float4 x = *(const float4*)(smem + OFF_STAGE + (size_t)i * 16);
            int row = i >> 5, c4 = i & 31;
            *(uint2*)(smem + OFF_X0 + xoff + (uint32_t)row * ROWB + (uint32_t)c4 * 8)
                = make_uint2(pack_h2(x.x, x.y), pack_h2(x.z, x.w));
        }
        __syncthreads();   // f16[parity] ready; staging fully consumed

        // ---- prefetch next tile into staging via cp.async (no registers) ----
        int sn = s + NCTA;
        if (sn < S_LEN) {
            const char* src = (const char*)(seq + (size_t)sn * B_SZ * EMB) + tid * 16;
            uint32_t dst = stage_b + tid * 16;
            #pragma unroll
            for (int ii = 0; ii < 8; ii++)
                CP_ASYNC16(dst + ii * 4096, src + ii * 4096);
            CP_COMMIT();
        }

        // ---- GEMM: acc = A*B (B from registers) ----
        float acc[2][4][4];
        #pragma unroll
        for (int i = 0; i < 2; i++)
            #pragma unroll
            for (int nt = 0; nt < 4; nt++)
                #pragma unroll
                for (int qq = 0; qq < 4; qq++) acc[i][nt][qq] = 0.f;

        const uint32_t a_ad = a_base + xoff;
        #pragma unroll
        for (int k = 0; k < 8; k++) {
            uint32_t a0[4], a1[4];
            LDSM4(a0, a_ad + (uint32_t)k * 32);
            LDSM4(a1, a_ad + 16 * ROWB + (uint32_t)k * 32);
            #pragma unroll
            for (int p = 0; p < 2; p++) {
                MMA16816(acc[0][2 * p],     a0, bfr[p][k][0], bfr[p][k][1]);
                MMA16816(acc[0][2 * p + 1], a0, bfr[p][k][2], bfr[p][k][3]);
                MMA16816(acc[1][2 * p],     a1, bfr[p][k][0], bfr[p][k][1]);
                MMA16816(acc[1][2 * p + 1], a1, bfr[p][k][2], bfr[p][k][3]);
            }
        }

        // ---- epilogue: +hp, tanh.approx, v-dot, quad reduce ----
        #pragma unroll
        for (int i = 0; i < 2; i++) {
            uint4 wa = *(const uint4*)(hpb + i * 32);
            uint4 wb = *(const uint4*)(hpb + i * 32 + 16);
            uint32_t w01[4] = { wa.x, wa.z, wb.x, wb.z };
            uint32_t w23[4] = { wa.y, wa.w, wb.y, wb.w };
            float p0 = 0.f, p1 = 0.f;
            #pragma unroll
            for (int nt = 0; nt < 4; nt++) {
                int c0 = nq * 32 + nt * 8 + 2 * q;
                float v0 = vs[c0], v1 = vs[c0 + 1];
                float2 hA = unpack_h2(w01[nt]);
                float2 hB = unpack_h2(w23[nt]);
                p0 = fmaf(v0, tanh_approx(acc[i][nt][0] + hA.x), p0);
                p0 = fmaf(v1, tanh_approx(acc[i][nt][1] + hA.y), p0);
                p1 = fmaf(v0, tanh_approx(acc[i][nt][2] + hB.x), p1);
                p1 = fmaf(v1, tanh_approx(acc[i][nt][3] + hB.y), p1);
            }
            p0 += __shfl_xor_sync(0xffffffffu, p0, 1);
            p0 += __shfl_xor_sync(0xffffffffu, p0, 2);
            p1 += __shfl_xor_sync(0xffffffffu, p1, 1);
            p1 += __shfl_xor_sync(0xffffffffu, p1, 2);
            if (q == 0) {
                int ra = mp * 32 + i * 16 + (lane >> 2);
                part[nq * 64 + ra] = p0;
                part[nq * 64 + ra + 8] = p1;
            }
        }
        CP_WAIT0();        // staging filled for next iter (own groups done)
        __syncthreads();   // part ready + all cp.asyncs visible CTA-wide
        if (tid < 64)
            g_scores[tid * S_LEN + s] = (part[tid] + part[64 + tid])
                                      + (part[128 + tid] + part[192 + tid]);
        parity ^= 1u;      // next convert writes other f16 buffer (no extra sync)
    }

    // ================= fused softmax (grid-wide sync via counter) ==========
    __threadfence();
    if (tid == 0) atomicAdd(&g_sync, 1);
    if (blockIdx.x >= B_SZ) return;

    if (tid == 0) {
        int v;
        do {
            asm volatile("ld.acquire.gpu.s32 %0, [%1];" : "=r"(v) : "l"(&g_sync) : "memory");
        } while (v < NCTA);
    }
    __syncthreads();

    float* ex = (float*)smem;            // 16 KB, smem now free
    __shared__ float red[8];
    const int b = blockIdx.x;
    const float* sc = g_scores + b * S_LEN;
    const int*   mk = mask + b * S_LEN;

    float mx = -1e30f;
    #pragma unroll
    for (int i = 0; i < 16; i++) {
        int s = tid + i * 256;
        float v = (mk[s] == 0) ? -1e10f : sc[s];
        ex[s] = v;
        mx = fmaxf(mx, v);
    }
    #pragma unroll
    for (int o = 16; o > 0; o >>= 1) mx = fmaxf(mx, __shfl_xor_sync(0xffffffffu, mx, o));
    if (lane == 0) red[wid] = mx;
    __syncthreads();
    if (tid < 8) {
        float m = red[tid];
        #pragma unroll
        for (int o = 4; o > 0; o >>= 1) m = fmaxf(m, __shfl_xor_sync(0xffu, m, o));
        red[tid] = m;
    }
    __syncthreads();
    mx = red[0];

    float sum = 0.f;
    #pragma unroll
    for (int i = 0; i < 16; i++) {
        int s = tid + i * 256;
        float e = __expf(ex[s] - mx);
        ex[s] = e;
        sum += e;
    }
    #pragma unroll
    for (int o = 16; o > 0; o >>= 1) sum += __shfl_xor_sync(0xffffffffu, sum, o);
    __syncthreads();
    if (lane == 0) red[wid] = sum;
    __syncthreads();
    if (tid < 8) {
        float m = red[tid];
        #pragma unroll
        for (int o = 4; o > 0; o >>= 1) m += __shfl_xor_sync(0xffu, m, o);
        red[tid] = m;
    }
    __syncthreads();
    float inv = 1.f / red[0];

    #pragma unroll
    for (int i = 0; i < 16; i++) {
        int s = tid + i * 256;
        out[b * S_LEN + s] = ex[s] * inv;
    }
}

// ---------------------------------------------------------------------------
extern "C" void kernel_launch(void* const* d_in, const int* in_sizes, int n_in,
                              void* d_out, int out_size) {
    const float* hidden = (const float*)d_in[0];
    const float* seq    = (const float*)d_in[1];
    const int*   mask   = (const int*)d_in[2];
    const float* W      = (const float*)d_in[3];
    const float* bias   = (const float*)d_in[4];
    const float* vw     = (const float*)d_in[5];
    float* out = (float*)d_out;

    cudaFuncSetAttribute(score_kernel, cudaFuncAttributeMaxDynamicSharedMemorySize, SMEM_BYTES);

    prep_kernel<<<96, 256>>>(hidden, W, bias);
    score_kernel<<<NCTA, 256, SMEM_BYTES>>>(seq, vw, mask, out);
}